// round 1
// baseline (speedup 1.0000x reference)
#include <cuda_runtime.h>
#include <math.h>
#include <stdint.h>

// Problem constants
#define BB  256
#define NN  1024
#define C1  101
#define DD  256
#define HH  16

#define NEGV (-1000000000.0f)

__device__ int g_mask_mode;                    // 0=uint8, 1=int32, 2=float32
__device__ __align__(16) float g_uv[BB * DD];
__device__ __align__(16) float g_uvc[BB * DD];

__device__ __forceinline__ bool readb(const void* p, int idx, int mode) {
    if (mode == 0) return ((const unsigned char*)p)[idx] != 0;
    if (mode == 1) return ((const int*)p)[idx] != 0;
    return ((const float*)p)[idx] != 0.0f;
}

// Detect bool serialization from the byte pattern of `mask` (bernoulli 0/1).
//  uint8 : 0/1 bytes at every position
//  int32 : 0/1 byte only at pos%4==0 (LE), rest zero
//  f32   : 1.0f = 00 00 80 3F -> 0x3f bytes present
__global__ void k_detect(const unsigned char* m) {
    if (threadIdx.x == 0 && blockIdx.x == 0) {
        bool f32 = false, u8 = false;
        for (int i = 0; i < 4096; i++) {
            unsigned char b = m[i];
            if (b == 0x3f) f32 = true;
            if ((i & 3) != 0 && b != 0) u8 = true;
        }
        g_mask_mode = f32 ? 2 : (u8 ? 0 : 1);
    }
}

// Kernel 1: fused masked means over node_embeddings (the only big HBM stream).
// One CTA per batch. 4 node-chunks x 64 float4-dim-columns.
__global__ void __launch_bounds__(256) k_nodes(
    const float* __restrict__ node, const void* __restrict__ mask,
    const void* __restrict__ cmask)
{
    __shared__ unsigned char code[NN];
    __shared__ int cnt[2];
    __shared__ float4 part[2][4][64];

    int b = blockIdx.x, t = threadIdx.x;
    int mode = g_mask_mode;

    if (t < 2) cnt[t] = 0;
    __syncthreads();

    int lc0 = 0, lc1 = 0;
    for (int i = t; i < NN; i += 256) {
        bool m  = readb(mask,  b * NN + i, mode);
        bool mc = m | readb(cmask, b * NN + i, mode);
        code[i] = (unsigned char)((m ? 1 : 0) | (mc ? 2 : 0));
        if (!m)  lc0++;
        if (!mc) lc1++;
    }
    atomicAdd(&cnt[0], lc0);
    atomicAdd(&cnt[1], lc1);
    __syncthreads();

    int chunk = t >> 6, d4 = t & 63;
    const float4* np4 = (const float4*)(node + (size_t)b * NN * DD);
    float4 s0 = make_float4(0.f, 0.f, 0.f, 0.f), s1 = s0;
    int n0 = chunk * 256;
#pragma unroll 4
    for (int n = n0; n < n0 + 256; n++) {
        float4 v = np4[n * 64 + d4];
        unsigned char c = code[n];
        if (!(c & 1)) { s0.x += v.x; s0.y += v.y; s0.z += v.z; s0.w += v.w; }
        if (!(c & 2)) { s1.x += v.x; s1.y += v.y; s1.z += v.z; s1.w += v.w; }
    }
    part[0][chunk][d4] = s0;
    part[1][chunk][d4] = s1;
    __syncthreads();

    if (t < 64) {
        float den0 = fmaxf((float)cnt[0], 1.0f);
        float den1 = fmaxf((float)cnt[1], 1.0f);
        float4 a, bb4, c4, dd4, r;

        a = part[0][0][t]; bb4 = part[0][1][t]; c4 = part[0][2][t]; dd4 = part[0][3][t];
        r.x = (a.x + bb4.x + c4.x + dd4.x) / den0;
        r.y = (a.y + bb4.y + c4.y + dd4.y) / den0;
        r.z = (a.z + bb4.z + c4.z + dd4.z) / den0;
        r.w = (a.w + bb4.w + c4.w + dd4.w) / den0;
        ((float4*)(g_uv + (size_t)b * DD))[t] = r;

        a = part[1][0][t]; bb4 = part[1][1][t]; c4 = part[1][2][t]; dd4 = part[1][3][t];
        r.x = (a.x + bb4.x + c4.x + dd4.x) / den1;
        r.y = (a.y + bb4.y + c4.y + dd4.y) / den1;
        r.z = (a.z + bb4.z + c4.z + dd4.z) / den1;
        r.w = (a.w + bb4.w + c4.w + dd4.w) / den1;
        ((float4*)(g_uvc + (size_t)b * DD))[t] = r;
    }
}

__device__ __forceinline__ float warp_dot256(const float* a, const float* b, int lane) {
    const float4* a4 = (const float4*)a;
    const float4* b4 = (const float4*)b;
    float4 x0 = a4[lane * 2], x1 = a4[lane * 2 + 1];
    float4 y0 = b4[lane * 2], y1 = b4[lane * 2 + 1];
    float s = x0.x * y0.x + x0.y * y0.y + x0.z * y0.z + x0.w * y0.w
            + x1.x * y1.x + x1.y * y1.y + x1.z * y1.z + x1.w * y1.w;
#pragma unroll
    for (int o = 16; o; o >>= 1) s += __shfl_xor_sync(0xffffffffu, s, o);
    return s;
}

// SMEM layout (floats):
//  ce 25856 | u 4096 | w 4096 | att 1632 | ctx 768 | q 256 | gl 256 | go 256 |
//  tv 256 | lg 104 | red 8 | vmi(int) 104 | seli(int) 4
#define SMEM_FLOATS (25856 + 4096 + 4096 + 1632 + 768 + 256 + 256 + 256 + 256 + 104 + 8 + 104 + 4)
#define SMEM_BYTES  (SMEM_FLOATS * 4)

// Kernel 2: one CTA per batch; everything after the node pass.
__global__ void __launch_bounds__(256, 1) k_main(
    const float* __restrict__ depot, const float* __restrict__ clus,
    const float* __restrict__ cur,   const void*  __restrict__ vmask,
    const float* __restrict__ Wq,    const float* __restrict__ Wk,
    const float* __restrict__ Wv,    const float* __restrict__ Wks,
    const float* __restrict__ Wo,    float* __restrict__ out)
{
    extern __shared__ float smem[];
    float* ce  = smem;
    float* u_s = ce  + 25856;
    float* w_s = u_s + 4096;
    float* att = w_s + 4096;
    float* ctx = att + 1632;
    float* q_s = ctx + 768;
    float* gl  = q_s + 256;
    float* go  = gl  + 256;
    float* tv  = go  + 256;
    float* lg  = tv  + 256;
    float* red = lg  + 104;
    int*   vmi  = (int*)(red + 8);
    int*   seli = vmi + 104;

    int b = blockIdx.x, t = threadIdx.x;
    int lane = t & 31, warp = t >> 5;
    int mode = g_mask_mode;

    // 1. cluster tile -> SMEM
    const float4* cg = (const float4*)(clus + (size_t)b * C1 * DD);
    float4* ce4 = (float4*)ce;
    for (int i = t; i < C1 * DD / 4; i += 256) ce4[i] = cg[i];

    // 2. visited mask + context
    if (t < C1) vmi[t] = readb(vmask, b * C1 + t, mode) ? 1 : 0;
    ctx[t]       = g_uv[(size_t)b * DD + t];
    ctx[256 + t] = cur[(size_t)b * DD + t];
    ctx[512 + t] = depot[(size_t)b * DD + t];
    __syncthreads();

    if (t == 0) {
        int all = 1;
        for (int j = 1; j < C1; j++) all &= vmi[j];
        vmi[0] = !all;
    }

    // 3. q = ctx @ Wq  (768x256)
    {
        float acc = 0.f;
#pragma unroll 8
        for (int i = 0; i < 768; i++) acc += ctx[i] * Wq[(size_t)i * 256 + t];
        q_s[t] = acc;
    }
    __syncthreads();

    // 4. u[h][d] = sum_e Wk[d, h*16+e] * q[h*16+e]
    {
        const float4* wkr = (const float4*)(Wk + (size_t)t * 256);
#pragma unroll
        for (int h = 0; h < HH; h++) {
            float a = 0.f;
#pragma unroll
            for (int e4 = 0; e4 < 4; e4++) {
                float4 wv = wkr[h * 4 + e4];
                const float* qp = q_s + h * 16 + e4 * 4;
                a += wv.x * qp[0] + wv.y * qp[1] + wv.z * qp[2] + wv.w * qp[3];
            }
            u_s[h * 256 + t] = a;
        }
    }
    __syncthreads();

    // 5. scores(h,j) = u_h . ce_j / 4, masked
    for (int p = warp; p < HH * C1; p += 8) {
        int h = p / C1, j = p - h * C1;
        float s = warp_dot256(u_s + h * 256, ce + j * 256, lane);
        if (lane == 0) att[p] = vmi[j] ? NEGV : s * 0.25f;
    }
    __syncthreads();

    // 6. softmax per head (warp w: heads w and w+8)
    for (int hh = 0; hh < 2; hh++) {
        int h = warp + 8 * hh;
        float v[4];
#pragma unroll
        for (int k = 0; k < 4; k++) {
            int j = lane + 32 * k;
            v[k] = (j < C1) ? att[h * C1 + j] : -3.0e38f;
        }
        float m = fmaxf(fmaxf(v[0], v[1]), fmaxf(v[2], v[3]));
#pragma unroll
        for (int o = 16; o; o >>= 1) m = fmaxf(m, __shfl_xor_sync(0xffffffffu, m, o));
        float e[4], s = 0.f;
#pragma unroll
        for (int k = 0; k < 4; k++) {
            int j = lane + 32 * k;
            e[k] = (j < C1) ? expf(v[k] - m) : 0.f;
            s += e[k];
        }
#pragma unroll
        for (int o = 16; o; o >>= 1) s += __shfl_xor_sync(0xffffffffu, s, o);
        float inv = 1.0f / s;
#pragma unroll
        for (int k = 0; k < 4; k++) {
            int j = lane + 32 * k;
            if (j < C1) att[h * C1 + j] = e[k] * inv;
        }
    }
    __syncthreads();

    // 7. w_h[d] = sum_j attn(h,j) * ce[j][d]
    for (int hh = 0; hh < 2; hh++) {
        int h = warp + 8 * hh;
        float4 A0 = make_float4(0.f, 0.f, 0.f, 0.f), A1 = A0;
        const float* ah = att + h * C1;
        for (int j = 0; j < C1; j++) {
            float a = ah[j];
            const float4* cj = (const float4*)(ce + j * 256);
            float4 b0 = cj[lane * 2], b1 = cj[lane * 2 + 1];
            A0.x += a * b0.x; A0.y += a * b0.y; A0.z += a * b0.z; A0.w += a * b0.w;
            A1.x += a * b1.x; A1.y += a * b1.y; A1.z += a * b1.z; A1.w += a * b1.w;
        }
        float4* wp = (float4*)(w_s + h * 256);
        wp[lane * 2] = A0;
        wp[lane * 2 + 1] = A1;
    }
    __syncthreads();

    // 8. glimpse[c] = sum_d Wv[d,c] * w_{c/16}[d]
    {
        int h = t >> 4;
        const float* wr = w_s + h * 256;
        float a = 0.f;
#pragma unroll 8
        for (int d = 0; d < 256; d++) a += Wv[(size_t)d * 256 + t] * wr[d];
        gl[t] = a;
    }
    __syncthreads();

    // 9. go = glimpse @ Wo
    {
        float a = 0.f;
#pragma unroll 8
        for (int d = 0; d < 256; d++) a += gl[d] * Wo[(size_t)d * 256 + t];
        go[t] = a;
    }
    __syncthreads();

    // 10. tv[d] = sum_c Wks[d,c] * go[c]   (row d per thread, float4)
    {
        const float4* wr = (const float4*)(Wks + (size_t)t * 256);
        const float4* gp = (const float4*)go;
        float a = 0.f;
#pragma unroll 8
        for (int c4 = 0; c4 < 64; c4++) {
            float4 wv = wr[c4];
            float4 g  = gp[c4];
            a += wv.x * g.x + wv.y * g.y + wv.z * g.z + wv.w * g.w;
        }
        tv[t] = a;
    }
    __syncthreads();

    // 11. logits[j] = tanh( (tv . ce_j) / 16 ) * 10, masked
    for (int j = warp; j < C1; j += 8) {
        float s = warp_dot256(tv, ce + j * 256, lane);
        if (lane == 0) {
            float l = tanhf(s * (1.0f / 16.0f)) * 10.0f;
            lg[j] = vmi[j] ? NEGV : l;
        }
    }
    __syncthreads();

    // 12. log_softmax + argmax (warp 0)
    if (warp == 0) {
        float m = -3.0e38f; int mi = 0x7fffffff;
        for (int j = lane; j < C1; j += 32) {
            float v = lg[j];
            if (v > m) { m = v; mi = j; }
        }
#pragma unroll
        for (int o = 16; o; o >>= 1) {
            float om = __shfl_xor_sync(0xffffffffu, m, o);
            int   oi = __shfl_xor_sync(0xffffffffu, mi, o);
            if (om > m || (om == m && oi < mi)) { m = om; mi = oi; }
        }
        float s = 0.f;
        for (int j = lane; j < C1; j += 32) s += expf(lg[j] - m);
#pragma unroll
        for (int o = 16; o; o >>= 1) s += __shfl_xor_sync(0xffffffffu, s, o);
        if (lane == 0) { red[0] = m + logf(s); seli[0] = mi; }
    }
    __syncthreads();

    // 13. outputs (float32 concat: init_aug | guidance_emb | guidance | clu_prob)
    int sel = seli[0];
    float lse = red[0];
    float se = ce[sel * 256 + t];
    size_t oa = (size_t)b * 1024;
    out[oa + t]        = g_uvc[(size_t)b * DD + t];
    out[oa + 256 + t]  = ctx[256 + t];     // current
    out[oa + 512 + t]  = se;               // selected cluster embedding
    out[oa + 768 + t]  = ctx[512 + t];     // depot
    out[262144 + (size_t)b * 256 + t] = se;
    if (t == 0) out[327680 + b] = (float)sel;
    if (t < C1) out[327936 + (size_t)b * C1 + t] = lg[t] - lse;
}

extern "C" void kernel_launch(void* const* d_in, const int* in_sizes, int n_in,
                              void* d_out, int out_size) {
    const float* depot = (const float*)d_in[0];
    const float* clus  = (const float*)d_in[1];
    const float* cur   = (const float*)d_in[2];
    const float* node  = (const float*)d_in[3];
    const void*  mask  = d_in[4];
    const void*  cmask = d_in[5];
    const void*  vmask = d_in[6];
    const float* Wq    = (const float*)d_in[7];
    const float* Wk    = (const float*)d_in[8];
    const float* Wv    = (const float*)d_in[9];
    const float* Wks   = (const float*)d_in[10];
    const float* Wo    = (const float*)d_in[11];
    float* out = (float*)d_out;

    cudaFuncSetAttribute(k_main, cudaFuncAttributeMaxDynamicSharedMemorySize, SMEM_BYTES);

    k_detect<<<1, 32>>>((const unsigned char*)mask);
    k_nodes<<<BB, 256>>>(node, mask, cmask);
    k_main<<<BB, 256, SMEM_BYTES>>>(depot, clus, cur, vmask, Wq, Wk, Wv, Wks, Wo, out);
}

// round 2
// speedup vs baseline: 1.5459x; 1.5459x over previous
#include <cuda_runtime.h>
#include <math.h>
#include <stdint.h>

// Problem constants
#define BB  256
#define NN  1024
#define C1  101
#define DD  256
#define HH  16

#define NEGV (-1000000000.0f)

__device__ __align__(16) float g_uv[BB * DD];
__device__ __align__(16) float g_uvc[BB * DD];
__device__ __align__(16) float g_u[BB * HH * DD];   // u[b][h][d]

__device__ __forceinline__ bool readb(const void* p, int idx, int mode) {
    if (mode == 0) return ((const unsigned char*)p)[idx] != 0;
    if (mode == 1) return ((const int*)p)[idx] != 0;
    return ((const float*)p)[idx] != 0.0f;
}

__device__ __forceinline__ float dot4(float4 a, float4 b) {
    return a.x * b.x + a.y * b.y + a.z * b.z + a.w * b.w;
}

// In-kernel bool-dtype detection: 256 threads probe first 4KB of `mask`
// (bernoulli 0/1 flags).  uint8: nonzero bytes at offsets %4!=0.
// float32: byte 0x3f present (1.0f = 00 00 80 3F). int32: neither.
// Must be called by all 256 threads (uses __syncthreads_or).
__device__ __forceinline__ int detect_mode(const void* m, int t) {
    uint4 v = ((const uint4*)m)[t];
    unsigned w[4] = {v.x, v.y, v.z, v.w};
    int f32 = 0, u8 = 0;
#pragma unroll
    for (int i = 0; i < 4; i++) {
        unsigned x = w[i];
        if (((x >> 24) & 0xffu) == 0x3fu || ((x >> 16) & 0xffu) == 0x3fu ||
            ((x >> 8) & 0xffu) == 0x3fu || (x & 0xffu) == 0x3fu) f32 = 1;
        if (x & 0xffffff00u) u8 = 1;
    }
    int a = __syncthreads_or(f32);
    int b = __syncthreads_or(u8);
    return a ? 2 : (b ? 0 : 1);
}

// Kernel 1: fused masked means over node_embeddings (the only big HBM stream).
__global__ void __launch_bounds__(256) k_nodes(
    const float* __restrict__ node, const void* __restrict__ mask,
    const void* __restrict__ cmask)
{
    __shared__ unsigned char code[NN];
    __shared__ int cnt[2];
    __shared__ float4 part[2][4][64];

    int b = blockIdx.x, t = threadIdx.x;
    int mode = detect_mode(mask, t);

    if (t < 2) cnt[t] = 0;
    __syncthreads();

    int lc0 = 0, lc1 = 0;
    for (int i = t; i < NN; i += 256) {
        bool m  = readb(mask,  b * NN + i, mode);
        bool mc = m | readb(cmask, b * NN + i, mode);
        code[i] = (unsigned char)((m ? 1 : 0) | (mc ? 2 : 0));
        if (!m)  lc0++;
        if (!mc) lc1++;
    }
    atomicAdd(&cnt[0], lc0);
    atomicAdd(&cnt[1], lc1);
    __syncthreads();

    int chunk = t >> 6, d4 = t & 63;
    const float4* np4 = (const float4*)(node + (size_t)b * NN * DD);
    float4 s0 = make_float4(0.f, 0.f, 0.f, 0.f), s1 = s0;
    int n0 = chunk * 256;
#pragma unroll 4
    for (int n = n0; n < n0 + 256; n++) {
        float4 v = np4[n * 64 + d4];
        unsigned char c = code[n];
        if (!(c & 1)) { s0.x += v.x; s0.y += v.y; s0.z += v.z; s0.w += v.w; }
        if (!(c & 2)) { s1.x += v.x; s1.y += v.y; s1.z += v.z; s1.w += v.w; }
    }
    part[0][chunk][d4] = s0;
    part[1][chunk][d4] = s1;
    __syncthreads();

    if (t < 64) {
        float den0 = fmaxf((float)cnt[0], 1.0f);
        float den1 = fmaxf((float)cnt[1], 1.0f);
        float4 a, bb4, c4, dd4, r;

        a = part[0][0][t]; bb4 = part[0][1][t]; c4 = part[0][2][t]; dd4 = part[0][3][t];
        r.x = (a.x + bb4.x + c4.x + dd4.x) / den0;
        r.y = (a.y + bb4.y + c4.y + dd4.y) / den0;
        r.z = (a.z + bb4.z + c4.z + dd4.z) / den0;
        r.w = (a.w + bb4.w + c4.w + dd4.w) / den0;
        ((float4*)(g_uv + (size_t)b * DD))[t] = r;

        a = part[1][0][t]; bb4 = part[1][1][t]; c4 = part[1][2][t]; dd4 = part[1][3][t];
        r.x = (a.x + bb4.x + c4.x + dd4.x) / den1;
        r.y = (a.y + bb4.y + c4.y + dd4.y) / den1;
        r.z = (a.z + bb4.z + c4.z + dd4.z) / den1;
        r.w = (a.w + bb4.w + c4.w + dd4.w) / den1;
        ((float4*)(g_uvc + (size_t)b * DD))[t] = r;
    }
}

// Kernel 2: batched q + u precompute.
// grid (4, 32): blockIdx.x = 64-col chunk (4 heads), blockIdx.y = 8-batch chunk.
// q[b,c] = ctx[b] @ Wq[:,c];  u[b,h,d] = sum_e Wk[d,h*16+e] * q[b,h*16+e].
__global__ void __launch_bounds__(256) k_qu(
    const float* __restrict__ cur, const float* __restrict__ depot,
    const float* __restrict__ Wq, const float* __restrict__ Wk)
{
    __shared__ __align__(16) float ctx_s[8][768];
    __shared__ __align__(16) float q_s[8][64];

    int cx = blockIdx.x;     // 0..3
    int by = blockIdx.y;     // 0..31
    int t = threadIdx.x;

    for (int i = t; i < 8 * 256; i += 256) {
        int bi = i >> 8, d = i & 255;
        int b = by * 8 + bi;
        ctx_s[bi][d]       = g_uv[(size_t)b * DD + d];
        ctx_s[bi][256 + d] = cur[(size_t)b * DD + d];
        ctx_s[bi][512 + d] = depot[(size_t)b * DD + d];
    }
    __syncthreads();

    int c = cx * 64 + (t & 63);
    int bg = t >> 6;   // 0..3 -> batches bg*2, bg*2+1
    {
        float acc0 = 0.f, acc1 = 0.f;
        const float* r0 = ctx_s[bg * 2];
        const float* r1 = ctx_s[bg * 2 + 1];
#pragma unroll 8
        for (int k = 0; k < 768; k++) {
            float w = Wq[(size_t)k * 256 + c];
            acc0 += w * r0[k];
            acc1 += w * r1[k];
        }
        q_s[bg * 2][t & 63]     = acc0;
        q_s[bg * 2 + 1][t & 63] = acc1;
    }
    __syncthreads();

    // u for heads cx*4 .. cx*4+3, all 8 batches; thread t = d.
    int d = t;
    const float4* wk = (const float4*)(Wk + (size_t)d * 256 + cx * 64);
#pragma unroll
    for (int hl = 0; hl < 4; hl++) {
        float4 w0 = wk[hl * 4], w1 = wk[hl * 4 + 1], w2 = wk[hl * 4 + 2], w3 = wk[hl * 4 + 3];
#pragma unroll
        for (int bi = 0; bi < 8; bi++) {
            const float4* qp = (const float4*)(&q_s[bi][hl * 16]);
            float4 q0 = qp[0], q1 = qp[1], q2 = qp[2], q3 = qp[3];
            float s = dot4(w0, q0) + dot4(w1, q1) + dot4(w2, q2) + dot4(w3, q3);
            g_u[(size_t)(by * 8 + bi) * (HH * DD) + (cx * 4 + hl) * 256 + d] = s;
        }
    }
}

// SMEM layout (floats):
//  ce 25856 | att 1632 | w 4096 | gl 256 | go 256 | tv 256 | lg 104 | red 8 |
//  vmi(int) 104 | seli(int) 4
#define SMEM_FLOATS (25856 + 4096 + 1632 + 256 + 256 + 256 + 104 + 8 + 104 + 4)
#define SMEM_BYTES  (SMEM_FLOATS * 4)

// Kernel 3: one CTA per batch; attention + glimpse chain + logits + outputs.
__global__ void __launch_bounds__(256, 1) k_main(
    const float* __restrict__ depot, const float* __restrict__ clus,
    const float* __restrict__ cur,   const void*  __restrict__ vmask,
    const void*  __restrict__ mask,
    const float* __restrict__ Wv,    const float* __restrict__ Wks,
    const float* __restrict__ Wo,    float* __restrict__ out)
{
    extern __shared__ float smem[];
    float* ce  = smem;          // 25856
    float* w_s = ce  + 25856;   // 4096
    float* att = w_s + 4096;    // 1632
    float* gl  = att + 1632;    // 256
    float* go  = gl  + 256;
    float* tv  = go  + 256;
    float* lg  = tv  + 256;     // 104
    float* red = lg  + 104;     // 8
    int*   vmi  = (int*)(red + 8);
    int*   seli = vmi + 104;

    int b = blockIdx.x, t = threadIdx.x;
    int lane = t & 31, warp = t >> 5;

    int mode = detect_mode(mask, t);

    // 1. cluster tile -> SMEM
    const float4* cg = (const float4*)(clus + (size_t)b * C1 * DD);
    float4* ce4 = (float4*)ce;
    for (int i = t; i < C1 * DD / 4; i += 256) ce4[i] = cg[i];

    // 2. visited mask
    if (t < C1) vmi[t] = readb(vmask, b * C1 + t, mode) ? 1 : 0;
    __syncthreads();
    if (t == 0) {
        int all = 1;
        for (int j = 1; j < C1; j++) all &= vmi[j];
        vmi[0] = !all;
    }
    __syncthreads();

    // 3. scores(h,j) = u_h . ce_j / 4, masked.
    // Warp w owns heads h0=w, h1=w+8; u slices live in registers.
    int h0 = warp, h1 = warp + 8;
    const float4* up = (const float4*)(g_u + (size_t)b * (HH * DD));
    float4 u00 = up[h0 * 64 + lane * 2], u01 = up[h0 * 64 + lane * 2 + 1];
    float4 u10 = up[h1 * 64 + lane * 2], u11 = up[h1 * 64 + lane * 2 + 1];

    const float4* ce4r = (const float4*)ce;
    for (int j = 0; j < 100; j += 2) {
        float4 a0 = ce4r[j * 64 + lane * 2],       a1 = ce4r[j * 64 + lane * 2 + 1];
        float4 b0 = ce4r[(j + 1) * 64 + lane * 2], b1 = ce4r[(j + 1) * 64 + lane * 2 + 1];
        float p00 = dot4(u00, a0) + dot4(u01, a1);
        float p10 = dot4(u10, a0) + dot4(u11, a1);
        float p01 = dot4(u00, b0) + dot4(u01, b1);
        float p11 = dot4(u10, b0) + dot4(u11, b1);
#pragma unroll
        for (int o = 16; o; o >>= 1) {
            p00 += __shfl_xor_sync(0xffffffffu, p00, o);
            p01 += __shfl_xor_sync(0xffffffffu, p01, o);
            p10 += __shfl_xor_sync(0xffffffffu, p10, o);
            p11 += __shfl_xor_sync(0xffffffffu, p11, o);
        }
        if (lane == 0) {
            att[h0 * C1 + j]     = vmi[j]     ? NEGV : p00 * 0.25f;
            att[h0 * C1 + j + 1] = vmi[j + 1] ? NEGV : p01 * 0.25f;
            att[h1 * C1 + j]     = vmi[j]     ? NEGV : p10 * 0.25f;
            att[h1 * C1 + j + 1] = vmi[j + 1] ? NEGV : p11 * 0.25f;
        }
    }
    {   // j = 100
        float4 a0 = ce4r[100 * 64 + lane * 2], a1 = ce4r[100 * 64 + lane * 2 + 1];
        float p00 = dot4(u00, a0) + dot4(u01, a1);
        float p10 = dot4(u10, a0) + dot4(u11, a1);
#pragma unroll
        for (int o = 16; o; o >>= 1) {
            p00 += __shfl_xor_sync(0xffffffffu, p00, o);
            p10 += __shfl_xor_sync(0xffffffffu, p10, o);
        }
        if (lane == 0) {
            att[h0 * C1 + 100] = vmi[100] ? NEGV : p00 * 0.25f;
            att[h1 * C1 + 100] = vmi[100] ? NEGV : p10 * 0.25f;
        }
    }
    __syncthreads();

    // 4. softmax per head (warp w: heads w and w+8)
#pragma unroll
    for (int hh = 0; hh < 2; hh++) {
        int h = warp + 8 * hh;
        float v[4];
#pragma unroll
        for (int k = 0; k < 4; k++) {
            int j = lane + 32 * k;
            v[k] = (j < C1) ? att[h * C1 + j] : -3.0e38f;
        }
        float m = fmaxf(fmaxf(v[0], v[1]), fmaxf(v[2], v[3]));
#pragma unroll
        for (int o = 16; o; o >>= 1) m = fmaxf(m, __shfl_xor_sync(0xffffffffu, m, o));
        float e[4], s = 0.f;
#pragma unroll
        for (int k = 0; k < 4; k++) {
            int j = lane + 32 * k;
            e[k] = (j < C1) ? expf(v[k] - m) : 0.f;
            s += e[k];
        }
#pragma unroll
        for (int o = 16; o; o >>= 1) s += __shfl_xor_sync(0xffffffffu, s, o);
        float inv = 1.0f / s;
#pragma unroll
        for (int k = 0; k < 4; k++) {
            int j = lane + 32 * k;
            if (j < C1) att[h * C1 + j] = e[k] * inv;
        }
    }
    __syncthreads();

    // 5. w_h[d] = sum_j attn(h,j) * ce[j][d]   (both heads in one ce pass)
    {
        float4 A00 = make_float4(0.f, 0.f, 0.f, 0.f), A01 = A00, A10 = A00, A11 = A00;
        const float* ah0 = att + h0 * C1;
        const float* ah1 = att + h1 * C1;
        for (int j = 0; j < C1; j++) {
            float a0 = ah0[j], a1 = ah1[j];
            float4 c0 = ce4r[j * 64 + lane * 2], c1 = ce4r[j * 64 + lane * 2 + 1];
            A00.x += a0 * c0.x; A00.y += a0 * c0.y; A00.z += a0 * c0.z; A00.w += a0 * c0.w;
            A01.x += a0 * c1.x; A01.y += a0 * c1.y; A01.z += a0 * c1.z; A01.w += a0 * c1.w;
            A10.x += a1 * c0.x; A10.y += a1 * c0.y; A10.z += a1 * c0.z; A10.w += a1 * c0.w;
            A11.x += a1 * c1.x; A11.y += a1 * c1.y; A11.z += a1 * c1.z; A11.w += a1 * c1.w;
        }
        float4* wp0 = (float4*)(w_s + h0 * 256);
        float4* wp1 = (float4*)(w_s + h1 * 256);
        wp0[lane * 2] = A00; wp0[lane * 2 + 1] = A01;
        wp1[lane * 2] = A10; wp1[lane * 2 + 1] = A11;
    }
    __syncthreads();

    // 6. glimpse[c] = sum_d Wv[d,c] * w_{c/16}[d]
    {
        int h = t >> 4;
        const float* wr = w_s + h * 256;
        float a = 0.f;
#pragma unroll 8
        for (int d = 0; d < 256; d++) a += Wv[(size_t)d * 256 + t] * wr[d];
        gl[t] = a;
    }
    __syncthreads();

    // 7. go = glimpse @ Wo
    {
        float a = 0.f;
#pragma unroll 8
        for (int d = 0; d < 256; d++) a += gl[d] * Wo[(size_t)d * 256 + t];
        go[t] = a;
    }
    __syncthreads();

    // 8. tv[d] = sum_c Wks[d,c] * go[c]
    {
        const float4* wr = (const float4*)(Wks + (size_t)t * 256);
        const float4* gp = (const float4*)go;
        float a = 0.f;
#pragma unroll 8
        for (int c4 = 0; c4 < 64; c4++) {
            float4 wv = wr[c4];
            float4 g  = gp[c4];
            a += wv.x * g.x + wv.y * g.y + wv.z * g.z + wv.w * g.w;
        }
        tv[t] = a;
    }
    __syncthreads();

    // 9. logits[j] = tanh((tv . ce_j)/16)*10, masked  (warp-strided over j)
    {
        const float4* tv4 = (const float4*)tv;
        float4 t0 = tv4[lane * 2], t1 = tv4[lane * 2 + 1];
        for (int j = warp; j < C1; j += 8) {
            float4 c0 = ce4r[j * 64 + lane * 2], c1 = ce4r[j * 64 + lane * 2 + 1];
            float s = dot4(t0, c0) + dot4(t1, c1);
#pragma unroll
            for (int o = 16; o; o >>= 1) s += __shfl_xor_sync(0xffffffffu, s, o);
            if (lane == 0) {
                float l = tanhf(s * (1.0f / 16.0f)) * 10.0f;
                lg[j] = vmi[j] ? NEGV : l;
            }
        }
    }
    __syncthreads();

    // 10. log_softmax + argmax (warp 0)
    if (warp == 0) {
        float m = -3.0e38f; int mi = 0x7fffffff;
        for (int j = lane; j < C1; j += 32) {
            float v = lg[j];
            if (v > m) { m = v; mi = j; }
        }
#pragma unroll
        for (int o = 16; o; o >>= 1) {
            float om = __shfl_xor_sync(0xffffffffu, m, o);
            int   oi = __shfl_xor_sync(0xffffffffu, mi, o);
            if (om > m || (om == m && oi < mi)) { m = om; mi = oi; }
        }
        float s = 0.f;
        for (int j = lane; j < C1; j += 32) s += expf(lg[j] - m);
#pragma unroll
        for (int o = 16; o; o >>= 1) s += __shfl_xor_sync(0xffffffffu, s, o);
        if (lane == 0) { red[0] = m + logf(s); seli[0] = mi; }
    }
    __syncthreads();

    // 11. outputs (float32 concat: init_aug | guidance_emb | guidance | clu_prob)
    int sel = seli[0];
    float lse = red[0];
    float se = ce[sel * 256 + t];
    size_t oa = (size_t)b * 1024;
    out[oa + t]        = g_uvc[(size_t)b * DD + t];
    out[oa + 256 + t]  = cur[(size_t)b * DD + t];
    out[oa + 512 + t]  = se;
    out[oa + 768 + t]  = depot[(size_t)b * DD + t];
    out[262144 + (size_t)b * 256 + t] = se;
    if (t == 0) out[327680 + b] = (float)sel;
    if (t < C1) out[327936 + (size_t)b * C1 + t] = lg[t] - lse;
}

extern "C" void kernel_launch(void* const* d_in, const int* in_sizes, int n_in,
                              void* d_out, int out_size) {
    const float* depot = (const float*)d_in[0];
    const float* clus  = (const float*)d_in[1];
    const float* cur   = (const float*)d_in[2];
    const float* node  = (const float*)d_in[3];
    const void*  mask  = d_in[4];
    const void*  cmask = d_in[5];
    const void*  vmask = d_in[6];
    const float* Wq    = (const float*)d_in[7];
    const float* Wk    = (const float*)d_in[8];
    const float* Wv    = (const float*)d_in[9];
    const float* Wks   = (const float*)d_in[10];
    const float* Wo    = (const float*)d_in[11];
    float* out = (float*)d_out;

    cudaFuncSetAttribute(k_main, cudaFuncAttributeMaxDynamicSharedMemorySize, SMEM_BYTES);

    k_nodes<<<BB, 256>>>(node, mask, cmask);
    k_qu<<<dim3(4, 32), 256>>>(cur, depot, Wq, Wk);
    k_main<<<BB, 256, SMEM_BYTES>>>(depot, clus, cur, vmask, mask, Wv, Wks, Wo, out);
}

// round 3
// speedup vs baseline: 2.1068x; 1.3628x over previous
#include <cuda_runtime.h>
#include <math.h>
#include <stdint.h>

// Problem constants
#define BB  256
#define NN  1024
#define C1  101
#define DD  256
#define HH  16

#define NEGV (-1000000000.0f)

__device__ __align__(16) float g_uv[BB * DD];
__device__ __align__(16) float g_uvc[BB * DD];
__device__ __align__(16) float g_u[BB * HH * DD];   // u[b][h][d]

__device__ __forceinline__ bool readb(const void* p, int idx, int mode) {
    if (mode == 0) return ((const unsigned char*)p)[idx] != 0;
    if (mode == 1) return ((const int*)p)[idx] != 0;
    return ((const float*)p)[idx] != 0.0f;
}

__device__ __forceinline__ float dot4(float4 a, float4 b) {
    return a.x * b.x + a.y * b.y + a.z * b.z + a.w * b.w;
}

// In-kernel bool-dtype detection: threads probe first 4KB of `mask`
// (bernoulli 0/1 flags). uint8: nonzero bytes at offsets %4!=0.
// float32: byte 0x3f present (1.0f = 00 00 80 3F). int32: neither.
// Must be called by ALL threads of the block (uses __syncthreads_or).
__device__ __forceinline__ int detect_mode(const void* m, int t) {
    int f32 = 0, u8 = 0;
    if (t < 256) {
        uint4 v = ((const uint4*)m)[t];
        unsigned w[4] = {v.x, v.y, v.z, v.w};
#pragma unroll
        for (int i = 0; i < 4; i++) {
            unsigned x = w[i];
            if (((x >> 24) & 0xffu) == 0x3fu || ((x >> 16) & 0xffu) == 0x3fu ||
                ((x >> 8) & 0xffu) == 0x3fu || (x & 0xffu) == 0x3fu) f32 = 1;
            if (x & 0xffffff00u) u8 = 1;
        }
    }
    int a = __syncthreads_or(f32);
    int b = __syncthreads_or(u8);
    return a ? 2 : (b ? 0 : 1);
}

// Kernel 1: fused masked means over node_embeddings (the only big HBM stream).
// 512 threads: 8 node-chunks x 64 float4-dim-columns, 128 nodes per thread.
__global__ void __launch_bounds__(512) k_nodes(
    const float* __restrict__ node, const void* __restrict__ mask,
    const void* __restrict__ cmask)
{
    __shared__ unsigned char code[NN];
    __shared__ int cnt[2];
    __shared__ float4 part[2][8][64];

    int b = blockIdx.x, t = threadIdx.x;
    int mode = detect_mode(mask, t);

    if (t < 2) cnt[t] = 0;
    __syncthreads();

    int lc0 = 0, lc1 = 0;
    for (int i = t; i < NN; i += 512) {
        bool m  = readb(mask,  b * NN + i, mode);
        bool mc = m | readb(cmask, b * NN + i, mode);
        code[i] = (unsigned char)((m ? 1 : 0) | (mc ? 2 : 0));
        if (!m)  lc0++;
        if (!mc) lc1++;
    }
    atomicAdd(&cnt[0], lc0);
    atomicAdd(&cnt[1], lc1);
    __syncthreads();

    int chunk = t >> 6, d4 = t & 63;
    const float4* np4 = (const float4*)(node + (size_t)b * NN * DD);
    float4 s0 = make_float4(0.f, 0.f, 0.f, 0.f), s1 = s0;
    int n0 = chunk * 128;
#pragma unroll 8
    for (int n = n0; n < n0 + 128; n++) {
        float4 v = np4[n * 64 + d4];
        unsigned char c = code[n];
        if (!(c & 1)) { s0.x += v.x; s0.y += v.y; s0.z += v.z; s0.w += v.w; }
        if (!(c & 2)) { s1.x += v.x; s1.y += v.y; s1.z += v.z; s1.w += v.w; }
    }
    part[0][chunk][d4] = s0;
    part[1][chunk][d4] = s1;
    __syncthreads();

    if (t < 128) {
        int which = t >> 6;       // 0 -> uv, 1 -> uvc
        int d = t & 63;
        float den = fmaxf((float)cnt[which], 1.0f);
        float4 r = make_float4(0.f, 0.f, 0.f, 0.f);
#pragma unroll
        for (int c = 0; c < 8; c++) {
            float4 a = part[which][c][d];
            r.x += a.x; r.y += a.y; r.z += a.z; r.w += a.w;
        }
        r.x /= den; r.y /= den; r.z /= den; r.w /= den;
        float* dst = which ? g_uvc : g_uv;
        ((float4*)(dst + (size_t)b * DD))[d] = r;
    }
}

// Kernel 2: batched q + u precompute.
// grid (8, 32): blockIdx.x = 32-col chunk (2 heads), blockIdx.y = 8-batch chunk.
__global__ void __launch_bounds__(256) k_qu(
    const float* __restrict__ cur, const float* __restrict__ depot,
    const float* __restrict__ Wq, const float* __restrict__ Wk)
{
    __shared__ __align__(16) float ctx_s[8][768];
    __shared__ __align__(16) float q_s[8][32];

    int cx = blockIdx.x;     // 0..7
    int by = blockIdx.y;     // 0..31
    int t = threadIdx.x;

    for (int i = t; i < 8 * 256; i += 256) {
        int bi = i >> 8, d = i & 255;
        int b = by * 8 + bi;
        ctx_s[bi][d]       = g_uv[(size_t)b * DD + d];
        ctx_s[bi][256 + d] = cur[(size_t)b * DD + d];
        ctx_s[bi][512 + d] = depot[(size_t)b * DD + d];
    }
    __syncthreads();

    int c = cx * 32 + (t & 31);
    int bi = t >> 5;   // one batch per warp
    {
        float acc = 0.f;
        const float* r0 = ctx_s[bi];
#pragma unroll 16
        for (int k = 0; k < 768; k++)
            acc += Wq[(size_t)k * 256 + c] * r0[k];
        q_s[bi][t & 31] = acc;
    }
    __syncthreads();

    // u for heads cx*2, cx*2+1; thread t = d.
    int d = t;
    const float4* wk = (const float4*)(Wk + (size_t)d * 256 + cx * 32);
#pragma unroll
    for (int hl = 0; hl < 2; hl++) {
        float4 w0 = wk[hl * 4], w1 = wk[hl * 4 + 1], w2 = wk[hl * 4 + 2], w3 = wk[hl * 4 + 3];
#pragma unroll
        for (int bb = 0; bb < 8; bb++) {
            const float4* qp = (const float4*)(&q_s[bb][hl * 16]);
            float s = dot4(w0, qp[0]) + dot4(w1, qp[1]) + dot4(w2, qp[2]) + dot4(w3, qp[3]);
            g_u[(size_t)(by * 8 + bb) * (HH * DD) + (cx * 2 + hl) * 256 + d] = s;
        }
    }
}

// Kernel 3: one CTA per batch; attention + glimpse chain + logits + outputs.
// ce stays in gmem (L2-resident) -> small SMEM -> occ ~4 CTAs/SM -> one wave.
__global__ void __launch_bounds__(256, 4) k_main(
    const float* __restrict__ depot, const float* __restrict__ clus,
    const float* __restrict__ cur,   const void*  __restrict__ vmask,
    const void*  __restrict__ mask,
    const float* __restrict__ Wv,    const float* __restrict__ Wks,
    const float* __restrict__ Wo,    float* __restrict__ out)
{
    __shared__ __align__(16) float w_s[HH * DD];   // 4096
    __shared__ __align__(16) float att[HH * C1 + 12]; // 1628 pad
    __shared__ __align__(16) float gl[DD];
    __shared__ __align__(16) float go[DD];
    __shared__ __align__(16) float tv[DD];
    __shared__ float lg[C1 + 3];
    __shared__ float red[4];
    __shared__ int vmi[C1 + 3];
    __shared__ int seli[1];

    int b = blockIdx.x, t = threadIdx.x;
    int lane = t & 31, warp = t >> 5;

    int mode = detect_mode(mask, t);

    // visited mask
    if (t < C1) vmi[t] = readb(vmask, b * C1 + t, mode) ? 1 : 0;
    __syncthreads();
    if (t == 0) {
        int all = 1;
        for (int j = 1; j < C1; j++) all &= vmi[j];
        vmi[0] = !all;
    }
    __syncthreads();

    const float4* ce4r = (const float4*)(clus + (size_t)b * C1 * DD);

    // scores(h,j) = u_h . ce_j / 4, masked. Warp w: heads w, w+8.
    int h0 = warp, h1 = warp + 8;
    const float4* up = (const float4*)(g_u + (size_t)b * (HH * DD));
    float4 u00 = up[h0 * 64 + lane * 2], u01 = up[h0 * 64 + lane * 2 + 1];
    float4 u10 = up[h1 * 64 + lane * 2], u11 = up[h1 * 64 + lane * 2 + 1];

    for (int j = 0; j < 100; j += 2) {
        float4 a0 = ce4r[j * 64 + lane * 2],       a1 = ce4r[j * 64 + lane * 2 + 1];
        float4 b0 = ce4r[(j + 1) * 64 + lane * 2], b1 = ce4r[(j + 1) * 64 + lane * 2 + 1];
        float p00 = dot4(u00, a0) + dot4(u01, a1);
        float p10 = dot4(u10, a0) + dot4(u11, a1);
        float p01 = dot4(u00, b0) + dot4(u01, b1);
        float p11 = dot4(u10, b0) + dot4(u11, b1);
#pragma unroll
        for (int o = 16; o; o >>= 1) {
            p00 += __shfl_xor_sync(0xffffffffu, p00, o);
            p01 += __shfl_xor_sync(0xffffffffu, p01, o);
            p10 += __shfl_xor_sync(0xffffffffu, p10, o);
            p11 += __shfl_xor_sync(0xffffffffu, p11, o);
        }
        if (lane == 0) {
            att[h0 * C1 + j]     = vmi[j]     ? NEGV : p00 * 0.25f;
            att[h0 * C1 + j + 1] = vmi[j + 1] ? NEGV : p01 * 0.25f;
            att[h1 * C1 + j]     = vmi[j]     ? NEGV : p10 * 0.25f;
            att[h1 * C1 + j + 1] = vmi[j + 1] ? NEGV : p11 * 0.25f;
        }
    }
    {   // j = 100
        float4 a0 = ce4r[100 * 64 + lane * 2], a1 = ce4r[100 * 64 + lane * 2 + 1];
        float p00 = dot4(u00, a0) + dot4(u01, a1);
        float p10 = dot4(u10, a0) + dot4(u11, a1);
#pragma unroll
        for (int o = 16; o; o >>= 1) {
            p00 += __shfl_xor_sync(0xffffffffu, p00, o);
            p10 += __shfl_xor_sync(0xffffffffu, p10, o);
        }
        if (lane == 0) {
            att[h0 * C1 + 100] = vmi[100] ? NEGV : p00 * 0.25f;
            att[h1 * C1 + 100] = vmi[100] ? NEGV : p10 * 0.25f;
        }
    }
    __syncthreads();

    // softmax per head (warp w: heads w and w+8)
#pragma unroll
    for (int hh = 0; hh < 2; hh++) {
        int h = warp + 8 * hh;
        float v[4];
#pragma unroll
        for (int k = 0; k < 4; k++) {
            int j = lane + 32 * k;
            v[k] = (j < C1) ? att[h * C1 + j] : -3.0e38f;
        }
        float m = fmaxf(fmaxf(v[0], v[1]), fmaxf(v[2], v[3]));
#pragma unroll
        for (int o = 16; o; o >>= 1) m = fmaxf(m, __shfl_xor_sync(0xffffffffu, m, o));
        float e[4], s = 0.f;
#pragma unroll
        for (int k = 0; k < 4; k++) {
            int j = lane + 32 * k;
            e[k] = (j < C1) ? expf(v[k] - m) : 0.f;
            s += e[k];
        }
#pragma unroll
        for (int o = 16; o; o >>= 1) s += __shfl_xor_sync(0xffffffffu, s, o);
        float inv = 1.0f / s;
#pragma unroll
        for (int k = 0; k < 4; k++) {
            int j = lane + 32 * k;
            if (j < C1) att[h * C1 + j] = e[k] * inv;
        }
    }
    __syncthreads();

    // w_h[d] = sum_j attn(h,j) * ce[j][d]   (both heads in one ce pass)
    {
        float4 A00 = make_float4(0.f, 0.f, 0.f, 0.f), A01 = A00, A10 = A00, A11 = A00;
        const float* ah0 = att + h0 * C1;
        const float* ah1 = att + h1 * C1;
        for (int j = 0; j < C1; j++) {
            float a0 = ah0[j], a1 = ah1[j];
            float4 c0 = ce4r[j * 64 + lane * 2], c1 = ce4r[j * 64 + lane * 2 + 1];
            A00.x += a0 * c0.x; A00.y += a0 * c0.y; A00.z += a0 * c0.z; A00.w += a0 * c0.w;
            A01.x += a0 * c1.x; A01.y += a0 * c1.y; A01.z += a0 * c1.z; A01.w += a0 * c1.w;
            A10.x += a1 * c0.x; A10.y += a1 * c0.y; A10.z += a1 * c0.z; A10.w += a1 * c0.w;
            A11.x += a1 * c1.x; A11.y += a1 * c1.y; A11.z += a1 * c1.z; A11.w += a1 * c1.w;
        }
        float4* wp0 = (float4*)(w_s + h0 * 256);
        float4* wp1 = (float4*)(w_s + h1 * 256);
        wp0[lane * 2] = A00; wp0[lane * 2 + 1] = A01;
        wp1[lane * 2] = A10; wp1[lane * 2 + 1] = A11;
    }
    __syncthreads();

    // glimpse[c] = sum_d Wv[d,c] * w_{c/16}[d]
    {
        int h = t >> 4;
        const float* wr = w_s + h * 256;
        float a = 0.f;
#pragma unroll 16
        for (int d = 0; d < 256; d++) a += Wv[(size_t)d * 256 + t] * wr[d];
        gl[t] = a;
    }
    __syncthreads();

    // go = glimpse @ Wo
    {
        float a = 0.f;
#pragma unroll 16
        for (int d = 0; d < 256; d++) a += gl[d] * Wo[(size_t)d * 256 + t];
        go[t] = a;
    }
    __syncthreads();

    // tv[d] = sum_c Wks[d,c] * go[c]
    {
        const float4* wr = (const float4*)(Wks + (size_t)t * 256);
        const float4* gp = (const float4*)go;
        float a = 0.f;
#pragma unroll 16
        for (int c4 = 0; c4 < 64; c4++) {
            float4 wv = wr[c4];
            float4 g  = gp[c4];
            a += wv.x * g.x + wv.y * g.y + wv.z * g.z + wv.w * g.w;
        }
        tv[t] = a;
    }
    __syncthreads();

    // logits[j] = tanh((tv . ce_j)/16)*10, masked  (warp-strided over j)
    {
        const float4* tv4 = (const float4*)tv;
        float4 t0 = tv4[lane * 2], t1 = tv4[lane * 2 + 1];
        for (int j = warp; j < C1; j += 8) {
            float4 c0 = ce4r[j * 64 + lane * 2], c1 = ce4r[j * 64 + lane * 2 + 1];
            float s = dot4(t0, c0) + dot4(t1, c1);
#pragma unroll
            for (int o = 16; o; o >>= 1) s += __shfl_xor_sync(0xffffffffu, s, o);
            if (lane == 0) {
                float l = tanhf(s * (1.0f / 16.0f)) * 10.0f;
                lg[j] = vmi[j] ? NEGV : l;
            }
        }
    }
    __syncthreads();

    // log_softmax + argmax (warp 0)
    if (warp == 0) {
        float m = -3.0e38f; int mi = 0x7fffffff;
        for (int j = lane; j < C1; j += 32) {
            float v = lg[j];
            if (v > m) { m = v; mi = j; }
        }
#pragma unroll
        for (int o = 16; o; o >>= 1) {
            float om = __shfl_xor_sync(0xffffffffu, m, o);
            int   oi = __shfl_xor_sync(0xffffffffu, mi, o);
            if (om > m || (om == m && oi < mi)) { m = om; mi = oi; }
        }
        float s = 0.f;
        for (int j = lane; j < C1; j += 32) s += expf(lg[j] - m);
#pragma unroll
        for (int o = 16; o; o >>= 1) s += __shfl_xor_sync(0xffffffffu, s, o);
        if (lane == 0) { red[0] = m + logf(s); seli[0] = mi; }
    }
    __syncthreads();

    // outputs (float32 concat: init_aug | guidance_emb | guidance | clu_prob)
    int sel = seli[0];
    float lse = red[0];
    float se = clus[(size_t)b * C1 * DD + sel * 256 + t];
    size_t oa = (size_t)b * 1024;
    out[oa + t]        = g_uvc[(size_t)b * DD + t];
    out[oa + 256 + t]  = cur[(size_t)b * DD + t];
    out[oa + 512 + t]  = se;
    out[oa + 768 + t]  = depot[(size_t)b * DD + t];
    out[262144 + (size_t)b * 256 + t] = se;
    if (t == 0) out[327680 + b] = (float)sel;
    if (t < C1) out[327936 + (size_t)b * C1 + t] = lg[t] - lse;
}

extern "C" void kernel_launch(void* const* d_in, const int* in_sizes, int n_in,
                              void* d_out, int out_size) {
    const float* depot = (const float*)d_in[0];
    const float* clus  = (const float*)d_in[1];
    const float* cur   = (const float*)d_in[2];
    const float* node  = (const float*)d_in[3];
    const void*  mask  = d_in[4];
    const void*  cmask = d_in[5];
    const void*  vmask = d_in[6];
    const float* Wq    = (const float*)d_in[7];
    const float* Wk    = (const float*)d_in[8];
    const float* Wv    = (const float*)d_in[9];
    const float* Wks   = (const float*)d_in[10];
    const float* Wo    = (const float*)d_in[11];
    float* out = (float*)d_out;

    k_nodes<<<BB, 512>>>(node, mask, cmask);
    k_qu<<<dim3(8, 32), 256>>>(cur, depot, Wq, Wk);
    k_main<<<BB, 256>>>(depot, clus, cur, vmask, mask, Wv, Wks, Wo, out);
}